// round 15
// baseline (speedup 1.0000x reference)
#include <cuda_runtime.h>

#define T_    16384
#define NB    64
#define CIN   8
#define NH    32
#define NE    64
#define W_    32          // warm-up steps (2^-32 decay ~3 decades below fp32 ulp -> spike-exact)
#define LA_   256         // kA segment length
#define XSB   168         // kA phase buffer cols (162 staged max + dangling prefetch pad)
#define LB_   128         // kB segment length
#define MSZ   1064        // kB staged mask words per block (max index 1059)

typedef unsigned long long u64;

// Packed fp32 pair ops (f32x2; IEEE rn per half -> bit-identical to scalar).
__device__ __forceinline__ u64 pk2(float lo, float hi) {
    u64 r; asm("mov.b64 %0,{%1,%2};" : "=l"(r) : "f"(lo), "f"(hi)); return r;
}
__device__ __forceinline__ void upk2(u64 v, float& lo, float& hi) {
    asm("mov.b64 {%0,%1},%2;" : "=f"(lo), "=f"(hi) : "l"(v));
}
__device__ __forceinline__ u64 fma2_(u64 a, u64 b, u64 c) {
    u64 d; asm("fma.rn.f32x2 %0,%1,%2,%3;" : "=l"(d) : "l"(a), "l"(b), "l"(c)); return d;
}
__device__ __forceinline__ u64 add2_(u64 a, u64 b) {
    u64 d; asm("add.rn.f32x2 %0,%1,%2;" : "=l"(d) : "l"(a), "l"(b)); return d;
}
__device__ __forceinline__ u64 mul2_(u64 a, u64 b) {
    u64 d; asm("mul.rn.f32x2 %0,%1,%2;" : "=l"(d) : "l"(a), "l"(b)); return d;
}

// Layer-1 spike bitmasks: word (b,t), bit = channel h. (allocation-free contract)
__device__ unsigned g_mask[(size_t)NB * T_];

// ---------------------------------------------------------------------------
// kA: conv1(k=3,same) + BN1 + LIF1 -> g_mask.  One warp per (b, 256-seg);
// lane = channel h.  b = blockIdx.y + b0 (batch chunking for cross-stream
// overlap).  x window staged in smem in TWO phases (5.3KB).  Packed-pair
// conv; BN folded to one FMA (conv bias zero -> exact); 4-op LIF on
// post-reset state (tau=2 -> *0.5 exact).
// ---------------------------------------------------------------------------
__global__ void __launch_bounds__(32) kA(
    const float* __restrict__ x,  const float* __restrict__ w1,
    const float* __restrict__ b1, const float* __restrict__ g1,
    const float* __restrict__ be1,const float* __restrict__ m1,
    const float* __restrict__ v1, int b0)
{
    __shared__ __align__(16) float xs[XSB * CIN];
    const int lane = threadIdx.x;
    const int seg  = blockIdx.x;            // 0..63
    const int b    = blockIdx.y + b0;
    const int t0   = seg * LA_;

    u64 wp[3][4];
#pragma unroll
    for (int k = 0; k < 3; k++)
#pragma unroll
        for (int j = 0; j < 4; j++)
            wp[k][j] = pk2(__ldg(&w1[(lane * CIN + 2 * j) * 3 + k]),
                           __ldg(&w1[(lane * CIN + 2 * j + 1) * 3 + k]));
    const float bias = __ldg(&b1[lane]);    // zero in dataset; fold exactly
    const float sc = __fmul_rn(__ldg(&g1[lane]), __frsqrt_rn(__fadd_rn(__ldg(&v1[lane]), 1e-5f)));
    const float sh0 = __fsub_rn(__ldg(&be1[lane]), __fmul_rn(__ldg(&m1[lane]), sc));
    const float sh  = __fmaf_rn(bias, sc, sh0);

    const float* xb = x + (size_t)b * CIN * T_;
    float vr = 0.0f;                 // post-reset membrane
    unsigned mym = 0;
    unsigned* mp = g_mask + (size_t)b * T_ + t0;
    int grp = 0;

#define KA_STEP(Pa,Pb,Qa,Qb,Ra,Rb,La,Lb,OFF,DOEMIT,SI) { \
    La = *(const ulonglong2*)(pt + (OFF)); \
    Lb = *(const ulonglong2*)(pt + (OFF) + 4); \
    u64 c0 = mul2_(wp[0][0], Pa.x); \
    u64 c1 = mul2_(wp[1][0], Qa.x); \
    u64 c2 = mul2_(wp[2][0], Ra.x); \
    c0 = fma2_(wp[0][1], Pa.y, c0); \
    c1 = fma2_(wp[1][1], Qa.y, c1); \
    c2 = fma2_(wp[2][1], Ra.y, c2); \
    c0 = fma2_(wp[0][2], Pb.x, c0); \
    c1 = fma2_(wp[1][2], Qb.x, c1); \
    c2 = fma2_(wp[2][2], Rb.x, c2); \
    c0 = fma2_(wp[0][3], Pb.y, c0); \
    c1 = fma2_(wp[1][3], Qb.y, c1); \
    c2 = fma2_(wp[2][3], Rb.y, c2); \
    u64 s2 = add2_(c0, add2_(c1, c2)); \
    float s_lo, s_hi; upk2(s2, s_lo, s_hi); \
    float acc = __fadd_rn(s_lo, s_hi); \
    float u   = __fmaf_rn(acc, sc, sh); \
    float vp  = __fmaf_rn(__fsub_rn(u, vr), 0.5f, vr); \
    bool  spk = (vp >= 1.0f); \
    vr = spk ? 0.0f : vp; \
    if (DOEMIT) { unsigned bal = __ballot_sync(0xffffffffu, spk); \
                  if (lane == (SI)) mym = bal; } }

#define KA_QUAD(DOEMIT, SB) { \
    KA_STEP(Aa,Ab,Ba,Bb,Ca,Cb,Da,Db, 24, DOEMIT, (SB) + 0) \
    KA_STEP(Ba,Bb,Ca,Cb,Da,Db,Aa,Ab, 32, DOEMIT, (SB) + 1) \
    KA_STEP(Ca,Cb,Da,Db,Aa,Ab,Ba,Bb, 40, DOEMIT, (SB) + 2) \
    KA_STEP(Da,Db,Aa,Ab,Ba,Bb,Ca,Cb, 48, DOEMIT, (SB) + 3) \
    pt += 32; }

#pragma unroll 1
    for (int ph = 0; ph < 2; ph++) {
        // Phase 0: cols j <-> t = t0-33+j, 130 cols (32 warm + 96 emit).
        // Phase 1: cols j <-> t = t0+95+j, 162 cols (160 emit).
        const int tbase = (ph == 0) ? (t0 - 33) : (t0 + 95);
        const int ncols = (ph == 0) ? 130 : 162;
        __syncwarp();
#pragma unroll 1
        for (int j = lane; j < ncols; j += 32) {
            int t = tbase + j;
            bool ok = ((unsigned)t < (unsigned)T_);
            float v0 = ok ? __ldg(xb + 0 * T_ + t) : 0.0f;
            float v1_ = ok ? __ldg(xb + 1 * T_ + t) : 0.0f;
            float v2_ = ok ? __ldg(xb + 2 * T_ + t) : 0.0f;
            float v3_ = ok ? __ldg(xb + 3 * T_ + t) : 0.0f;
            float v4_ = ok ? __ldg(xb + 4 * T_ + t) : 0.0f;
            float v5_ = ok ? __ldg(xb + 5 * T_ + t) : 0.0f;
            float v6_ = ok ? __ldg(xb + 6 * T_ + t) : 0.0f;
            float v7_ = ok ? __ldg(xb + 7 * T_ + t) : 0.0f;
            *(float4*)&xs[j * 8]     = make_float4(v0, v1_, v2_, v3_);
            *(float4*)&xs[j * 8 + 4] = make_float4(v4_, v5_, v6_, v7_);
        }
        __syncwarp();

        // Prime window. Phase 0 seg==0 skips warm-up: start at col 32 (t=-1).
        const float* pt = xs + ((ph == 0 && seg == 0) ? 32 * 8 : 0);
        ulonglong2 Aa = *(const ulonglong2*)(pt + 0),  Ab = *(const ulonglong2*)(pt + 4);
        ulonglong2 Ba = *(const ulonglong2*)(pt + 8),  Bb = *(const ulonglong2*)(pt + 12);
        ulonglong2 Ca = *(const ulonglong2*)(pt + 16), Cb = *(const ulonglong2*)(pt + 20);
        ulonglong2 Da, Db;

        if (ph == 0 && seg != 0) {
#pragma unroll 1
            for (int q = 0; q < 8; q++) KA_QUAD(0, 0)       // 32 warm steps
        }
        const int ng = (ph == 0) ? 3 : 5;
#pragma unroll 1
        for (int g = 0; g < ng; g++) {
#pragma unroll 1
            for (int q = 0; q < 8; q++) KA_QUAD(1, q * 4)    // 32 emit steps
            mp[grp * 32 + lane] = mym;
            grp++;
        }
    }
#undef KA_QUAD
#undef KA_STEP
}

// ---------------------------------------------------------------------------
// kB: sparse conv2 + BN2 + LIF2 + output expansion -> out[B,E,T].
// Block = 8 warps = 8 consecutive 128-step segments of one batch;
// b = blockIdx.y + b0 (batch chunking for cross-stream overlap).
// __launch_bounds__(256,5): 48 regs.  Aligned uint4 mask reads; period-4
// accumulator renaming; split conflict-free weight tables; packed (e0,e1)
// accumulators; bit loop unrolled by 2; predicated spike-bit emit;
// 16-entry float4 nibble-LUT expansion.
// ---------------------------------------------------------------------------
__global__ void __launch_bounds__(256, 5) kB(
    const float* __restrict__ w2, const float* __restrict__ b2,
    const float* __restrict__ g2, const float* __restrict__ be2,
    const float* __restrict__ m2, const float* __restrict__ v2,
    float* __restrict__ out, int b0)
{
    __shared__ __align__(16) float4 ws4[NH * 32];  // [c][lane] = {k0e0,k0e1,k1e0,k1e1}
    __shared__ __align__(8)  float2 ws2[NH * 32];  // [c][lane] = {k2e0,k2e1}
    __shared__ __align__(16) unsigned ms[MSZ];
    __shared__ unsigned es[8][NE];                 // per-warp expansion staging
    __shared__ __align__(16) float4 lut16[16];     // nibble -> float4 0/1

    const int tid  = threadIdx.x;
    const int lane = tid & 31;
    const int w    = tid >> 5;
    const int b    = blockIdx.y + b0;
    const int tblk = blockIdx.x * (8 * LB_);

    for (int i = tid; i < NH * 32; i += 256) {
        int c = i >> 5, l = i & 31, e0 = l * 2;
        ws4[i] = make_float4(w2[(e0 * NH + c) * 3 + 0], w2[((e0 + 1) * NH + c) * 3 + 0],
                             w2[(e0 * NH + c) * 3 + 1], w2[((e0 + 1) * NH + c) * 3 + 1]);
        ws2[i] = make_float2(w2[(e0 * NH + c) * 3 + 2], w2[((e0 + 1) * NH + c) * 3 + 2]);
    }
    for (int j = tid; j < MSZ; j += 256) {
        int t = tblk + j - 35;                     // ms[j] <-> mask word at time t
        ms[j] = ((unsigned)t < (unsigned)T_) ? g_mask[(size_t)b * T_ + t] : 0u;
    }
    if (tid < 16)
        lut16[tid] = make_float4((float)(tid & 1), (float)((tid >> 1) & 1),
                                 (float)((tid >> 2) & 1), (float)((tid >> 3) & 1));
    __syncthreads();

    const int segg = blockIdx.x * 8 + w;     // global 128-step segment id
    const int t0   = tblk + w * LB_;
    const unsigned* msw = ms + w * LB_;      // msw[j] <-> time t0 + j - 35
    const int e0   = lane * 2;

    const float sc0 = __fmul_rn(g2[e0],     __frsqrt_rn(__fadd_rn(v2[e0],     1e-5f)));
    const float sh0 = __fsub_rn(be2[e0],     __fmul_rn(m2[e0],     sc0));
    const float sc1 = __fmul_rn(g2[e0 + 1], __frsqrt_rn(__fadd_rn(v2[e0 + 1], 1e-5f)));
    const float sh1 = __fsub_rn(be2[e0 + 1], __fmul_rn(m2[e0 + 1], sc1));
    const u64 sc2 = pk2(sc0, sc1);
    const u64 sh2 = pk2(__fmaf_rn(b2[e0], sc0, sh0), __fmaf_rn(b2[e0 + 1], sc1, sh1));

    u64 aA = 0ull, aB = 0ull, aC = 0ull, aD = 0ull;   // packed (e0,e1) accumulators
    float vr0 = 0.f, vr1 = 0.f;                        // post-reset membranes
    unsigned me = 0, mo = 0;

    // Prime: word m[ts-1] -> tap0 to first emit acc; word m[ts] -> tap1 + tap0.
    const int pj = (segg == 0) ? 34 : 2;     // seg0: words t0-1,t0 ; else t0-33,t0-32
    { unsigned r = msw[pj];
      while (r) { int c = __ffs(r) - 1; r &= r - 1;
          ulonglong2 q = *(const ulonglong2*)&ws4[(c << 5) + lane];
          aA = add2_(aA, q.x); } }
    { unsigned r = msw[pj + 1];
      while (r) { int c = __ffs(r) - 1; r &= r - 1;
          ulonglong2 q = *(const ulonglong2*)&ws4[(c << 5) + lane];
          aA = add2_(aA, q.y);
          aB = add2_(aB, q.x); } }

#define KB_BIT(P_,Q_,R_) { \
    int c = __ffs(r) - 1; r &= r - 1; \
    ulonglong2 q = *(const ulonglong2*)&ws4[(c << 5) + lane]; \
    u64 p = *(const u64*)&ws2[(c << 5) + lane]; \
    P_ = add2_(P_, p); \
    Q_ = add2_(Q_, q.y); \
    R_ = add2_(R_, q.x); }

    // One LIF step: P = finished acc (gets tap2), Q gets tap1, R fresh (tap0).
#define KB_ST(P_,Q_,R_, RM, DOEMIT, SI) { \
    R_ = 0ull; \
    unsigned r = (RM); \
    while (r) { \
        KB_BIT(P_,Q_,R_) \
        if (r) { KB_BIT(P_,Q_,R_) } \
    } \
    u64 u2 = fma2_(P_, sc2, sh2); \
    float u0, u1; upk2(u2, u0, u1); \
    float vp0 = __fmaf_rn(__fsub_rn(u0, vr0), 0.5f, vr0); \
    bool  s0_ = (vp0 >= 1.0f);  vr0 = s0_ ? 0.0f : vp0; \
    float vp1 = __fmaf_rn(__fsub_rn(u1, vr1), 0.5f, vr1); \
    bool  s1_ = (vp1 >= 1.0f);  vr1 = s1_ ? 0.0f : vp1; \
    if (DOEMIT) { if (s0_) me |= (1u << (SI)); \
                  if (s1_) mo |= (1u << (SI)); } }

#define KB_QUAD(JQ, DOEMIT, SB) { \
    uint4 m4 = *(const uint4*)&msw[JQ]; \
    KB_ST(aA, aB, aC, m4.x, DOEMIT, (SB) + 0) \
    KB_ST(aB, aC, aD, m4.y, DOEMIT, (SB) + 1) \
    KB_ST(aC, aD, aA, m4.z, DOEMIT, (SB) + 2) \
    KB_ST(aD, aA, aB, m4.w, DOEMIT, (SB) + 3) }

    if (segg != 0) {
#pragma unroll 1
        for (int q = 0; q < 8; q++) KB_QUAD(4 + q * 4, 0, 0)      // 32 warm steps
    }

    float* ob = out + (size_t)b * NE * T_ + t0;
#pragma unroll 1
    for (int g = 0; g < 4; g++) {
        const int jb = 36 + g * 32;
#pragma unroll 1
        for (int q = 0; q < 8; q++) KB_QUAD(jb + q * 4, 1, q * 4)  // 32 emit steps

        *(uint2*)&es[w][e0] = make_uint2(me, mo);
        __syncwarp();
#pragma unroll
        for (int i = 0; i < 16; i++) {
            int idx = i * 32 + lane;          // 0..511
            int e   = idx >> 3;               // 0..63
            int q4  = (idx & 7) * 4;          // 0,4,..,28
            float4 v = lut16[(es[w][e] >> q4) & 0xF];
            *(float4*)&ob[(size_t)e * T_ + g * 32 + q4] = v;
        }
        __syncwarp();
        me = 0; mo = 0;
    }
#undef KB_QUAD
#undef KB_ST
#undef KB_BIT
}

// ---------------------------------------------------------------------------
// Launch schedule: split batches into two 32-batch chunks and overlap
// kB(chunk0) with kA(chunk1) via a forked stream (event fork/join — the
// standard multi-stream graph-capture pattern).  Dependency is exact:
// kB chunk i reads only g_mask rows written by kA chunk i.
// ---------------------------------------------------------------------------
extern "C" void kernel_launch(void* const* d_in, const int* in_sizes, int n_in,
                              void* d_out, int out_size)
{
    const float* x   = (const float*)d_in[0];
    const float* w1  = (const float*)d_in[1];
    const float* b1  = (const float*)d_in[2];
    const float* g1  = (const float*)d_in[3];
    const float* be1 = (const float*)d_in[4];
    const float* m1  = (const float*)d_in[5];
    const float* v1  = (const float*)d_in[6];
    const float* w2  = (const float*)d_in[7];
    const float* b2  = (const float*)d_in[8];
    const float* g2  = (const float*)d_in[9];
    const float* be2 = (const float*)d_in[10];
    const float* m2  = (const float*)d_in[11];
    const float* v2  = (const float*)d_in[12];
    float* out = (float*)d_out;

    cudaStream_t s2;
    cudaEvent_t evA0, evB0;
    cudaStreamCreateWithFlags(&s2, cudaStreamNonBlocking);
    cudaEventCreateWithFlags(&evA0, cudaEventDisableTiming);
    cudaEventCreateWithFlags(&evB0, cudaEventDisableTiming);

    // Chunk 0 of layer 1 (batches 0..31) on the main stream.
    kA<<<dim3(64, 32), 32>>>(x, w1, b1, g1, be1, m1, v1, 0);
    cudaEventRecord(evA0, 0);

    // Chunk 1 of layer 1 (batches 32..63) continues on the main stream...
    kA<<<dim3(64, 32), 32>>>(x, w1, b1, g1, be1, m1, v1, 32);

    // ...while chunk 0 of layer 2 runs concurrently on the forked stream.
    cudaStreamWaitEvent(s2, evA0, 0);
    kB<<<dim3(16, 32), 256, 0, s2>>>(w2, b2, g2, be2, m2, v2, out, 0);
    cudaEventRecord(evB0, s2);

    // Chunk 1 of layer 2 on the main stream (after kA chunk 1 by stream order).
    kB<<<dim3(16, 32), 256>>>(w2, b2, g2, be2, m2, v2, out, 32);

    // Join: main stream waits for the forked kB chunk.
    cudaStreamWaitEvent(0, evB0, 0);

    // Destroy only when not capturing (destroying a capture-participating
    // stream/event would invalidate the graph; the capture call leaks one
    // stream+2 events once, host-side).
    cudaStreamCaptureStatus st = cudaStreamCaptureStatusNone;
    cudaStreamIsCapturing(0, &st);
    if (st == cudaStreamCaptureStatusNone) {
        cudaStreamDestroy(s2);
        cudaEventDestroy(evA0);
        cudaEventDestroy(evB0);
    }
}

// round 16
// speedup vs baseline: 1.0447x; 1.0447x over previous
#include <cuda_runtime.h>

#define T_    16384
#define NB    64
#define CIN   8
#define NH    32
#define NE    64
#define W_    32          // warm-up steps (2^-32 decay ~3 decades below fp32 ulp -> spike-exact)
#define LA_   256         // kA segment length
#define XSB   168         // kA phase buffer cols (162 staged max + dangling prefetch pad)
#define LB_   256         // kB segment length (25% -> 12.5% warm-up overhead vs R13)
#define MSZ   2096        // kB staged mask words per block (max index 2083)

typedef unsigned long long u64;

// Packed fp32 pair ops (f32x2; IEEE rn per half -> bit-identical to scalar).
__device__ __forceinline__ u64 pk2(float lo, float hi) {
    u64 r; asm("mov.b64 %0,{%1,%2};" : "=l"(r) : "f"(lo), "f"(hi)); return r;
}
__device__ __forceinline__ void upk2(u64 v, float& lo, float& hi) {
    asm("mov.b64 {%0,%1},%2;" : "=f"(lo), "=f"(hi) : "l"(v));
}
__device__ __forceinline__ u64 fma2_(u64 a, u64 b, u64 c) {
    u64 d; asm("fma.rn.f32x2 %0,%1,%2,%3;" : "=l"(d) : "l"(a), "l"(b), "l"(c)); return d;
}
__device__ __forceinline__ u64 add2_(u64 a, u64 b) {
    u64 d; asm("add.rn.f32x2 %0,%1,%2;" : "=l"(d) : "l"(a), "l"(b)); return d;
}
__device__ __forceinline__ u64 mul2_(u64 a, u64 b) {
    u64 d; asm("mul.rn.f32x2 %0,%1,%2;" : "=l"(d) : "l"(a), "l"(b)); return d;
}

// Layer-1 spike bitmasks: word (b,t), bit = channel h. (allocation-free contract)
__device__ unsigned g_mask[(size_t)NB * T_];

// ---------------------------------------------------------------------------
// kA: conv1(k=3,same) + BN1 + LIF1 -> g_mask.  One warp per (b, 256-seg);
// lane = channel h.  x window staged in smem in TWO phases (5.3KB).
// Packed-pair conv (12 FFMA2-class ops); BN folded to one FMA (conv bias
// zero -> exact); 4-op LIF on post-reset state (tau=2 -> *0.5 exact).
// (R13-exact; measured ~59.4us.)
// ---------------------------------------------------------------------------
__global__ void __launch_bounds__(32) kA(
    const float* __restrict__ x,  const float* __restrict__ w1,
    const float* __restrict__ b1, const float* __restrict__ g1,
    const float* __restrict__ be1,const float* __restrict__ m1,
    const float* __restrict__ v1)
{
    __shared__ __align__(16) float xs[XSB * CIN];
    const int lane = threadIdx.x;
    const int seg  = blockIdx.x;            // 0..63
    const int b    = blockIdx.y;
    const int t0   = seg * LA_;

    u64 wp[3][4];
#pragma unroll
    for (int k = 0; k < 3; k++)
#pragma unroll
        for (int j = 0; j < 4; j++)
            wp[k][j] = pk2(__ldg(&w1[(lane * CIN + 2 * j) * 3 + k]),
                           __ldg(&w1[(lane * CIN + 2 * j + 1) * 3 + k]));
    const float bias = __ldg(&b1[lane]);    // zero in dataset; fold exactly
    const float sc = __fmul_rn(__ldg(&g1[lane]), __frsqrt_rn(__fadd_rn(__ldg(&v1[lane]), 1e-5f)));
    const float sh0 = __fsub_rn(__ldg(&be1[lane]), __fmul_rn(__ldg(&m1[lane]), sc));
    const float sh  = __fmaf_rn(bias, sc, sh0);

    const float* xb = x + (size_t)b * CIN * T_;
    float vr = 0.0f;                 // post-reset membrane
    unsigned mym = 0;
    unsigned* mp = g_mask + (size_t)b * T_ + t0;
    int grp = 0;

#define KA_STEP(Pa,Pb,Qa,Qb,Ra,Rb,La,Lb,OFF,DOEMIT,SI) { \
    La = *(const ulonglong2*)(pt + (OFF)); \
    Lb = *(const ulonglong2*)(pt + (OFF) + 4); \
    u64 c0 = mul2_(wp[0][0], Pa.x); \
    u64 c1 = mul2_(wp[1][0], Qa.x); \
    u64 c2 = mul2_(wp[2][0], Ra.x); \
    c0 = fma2_(wp[0][1], Pa.y, c0); \
    c1 = fma2_(wp[1][1], Qa.y, c1); \
    c2 = fma2_(wp[2][1], Ra.y, c2); \
    c0 = fma2_(wp[0][2], Pb.x, c0); \
    c1 = fma2_(wp[1][2], Qb.x, c1); \
    c2 = fma2_(wp[2][2], Rb.x, c2); \
    c0 = fma2_(wp[0][3], Pb.y, c0); \
    c1 = fma2_(wp[1][3], Qb.y, c1); \
    c2 = fma2_(wp[2][3], Rb.y, c2); \
    u64 s2 = add2_(c0, add2_(c1, c2)); \
    float s_lo, s_hi; upk2(s2, s_lo, s_hi); \
    float acc = __fadd_rn(s_lo, s_hi); \
    float u   = __fmaf_rn(acc, sc, sh); \
    float vp  = __fmaf_rn(__fsub_rn(u, vr), 0.5f, vr); \
    bool  spk = (vp >= 1.0f); \
    vr = spk ? 0.0f : vp; \
    if (DOEMIT) { unsigned bal = __ballot_sync(0xffffffffu, spk); \
                  if (lane == (SI)) mym = bal; } }

#define KA_QUAD(DOEMIT, SB) { \
    KA_STEP(Aa,Ab,Ba,Bb,Ca,Cb,Da,Db, 24, DOEMIT, (SB) + 0) \
    KA_STEP(Ba,Bb,Ca,Cb,Da,Db,Aa,Ab, 32, DOEMIT, (SB) + 1) \
    KA_STEP(Ca,Cb,Da,Db,Aa,Ab,Ba,Bb, 40, DOEMIT, (SB) + 2) \
    KA_STEP(Da,Db,Aa,Ab,Ba,Bb,Ca,Cb, 48, DOEMIT, (SB) + 3) \
    pt += 32; }

#pragma unroll 1
    for (int ph = 0; ph < 2; ph++) {
        // Phase 0: cols j <-> t = t0-33+j, 130 cols (32 warm + 96 emit).
        // Phase 1: cols j <-> t = t0+95+j, 162 cols (160 emit).
        const int tbase = (ph == 0) ? (t0 - 33) : (t0 + 95);
        const int ncols = (ph == 0) ? 130 : 162;
        __syncwarp();
#pragma unroll 1
        for (int j = lane; j < ncols; j += 32) {
            int t = tbase + j;
            bool ok = ((unsigned)t < (unsigned)T_);
            float v0 = ok ? __ldg(xb + 0 * T_ + t) : 0.0f;
            float v1_ = ok ? __ldg(xb + 1 * T_ + t) : 0.0f;
            float v2_ = ok ? __ldg(xb + 2 * T_ + t) : 0.0f;
            float v3_ = ok ? __ldg(xb + 3 * T_ + t) : 0.0f;
            float v4_ = ok ? __ldg(xb + 4 * T_ + t) : 0.0f;
            float v5_ = ok ? __ldg(xb + 5 * T_ + t) : 0.0f;
            float v6_ = ok ? __ldg(xb + 6 * T_ + t) : 0.0f;
            float v7_ = ok ? __ldg(xb + 7 * T_ + t) : 0.0f;
            *(float4*)&xs[j * 8]     = make_float4(v0, v1_, v2_, v3_);
            *(float4*)&xs[j * 8 + 4] = make_float4(v4_, v5_, v6_, v7_);
        }
        __syncwarp();

        // Prime window. Phase 0 seg==0 skips warm-up: start at col 32 (t=-1).
        const float* pt = xs + ((ph == 0 && seg == 0) ? 32 * 8 : 0);
        ulonglong2 Aa = *(const ulonglong2*)(pt + 0),  Ab = *(const ulonglong2*)(pt + 4);
        ulonglong2 Ba = *(const ulonglong2*)(pt + 8),  Bb = *(const ulonglong2*)(pt + 12);
        ulonglong2 Ca = *(const ulonglong2*)(pt + 16), Cb = *(const ulonglong2*)(pt + 20);
        ulonglong2 Da, Db;

        if (ph == 0 && seg != 0) {
#pragma unroll 1
            for (int q = 0; q < 8; q++) KA_QUAD(0, 0)       // 32 warm steps
        }
        const int ng = (ph == 0) ? 3 : 5;
#pragma unroll 1
        for (int g = 0; g < ng; g++) {
#pragma unroll 1
            for (int q = 0; q < 8; q++) KA_QUAD(1, q * 4)    // 32 emit steps
            mp[grp * 32 + lane] = mym;
            grp++;
        }
    }
#undef KA_QUAD
#undef KA_STEP
}

// ---------------------------------------------------------------------------
// kB: sparse conv2 + BN2 + LIF2 + output expansion -> out[B,E,T].
// Block = 8 warps = 8 consecutive 256-step segments of one batch; grid
// (8,64) = 512 blocks -> with 48 regs + max smem carveout, 5 blocks/SM fit:
// ALL blocks resident in ONE wave, and warm-up overhead drops 25% -> 12.5%.
// Aligned uint4 mask reads; period-4 accumulator renaming; split
// conflict-free weight tables; packed (e0,e1) accumulators; bit loop
// unrolled by 2; predicated spike-bit emit; float4 nibble-LUT expansion.
// ---------------------------------------------------------------------------
__global__ void __launch_bounds__(256, 5) kB(
    const float* __restrict__ w2, const float* __restrict__ b2,
    const float* __restrict__ g2, const float* __restrict__ be2,
    const float* __restrict__ m2, const float* __restrict__ v2,
    float* __restrict__ out)
{
    __shared__ __align__(16) float4 ws4[NH * 32];  // [c][lane] = {k0e0,k0e1,k1e0,k1e1}
    __shared__ __align__(8)  float2 ws2[NH * 32];  // [c][lane] = {k2e0,k2e1}
    __shared__ __align__(16) unsigned ms[MSZ];
    __shared__ unsigned es[8][NE];                 // per-warp expansion staging
    __shared__ __align__(16) float4 lut16[16];     // nibble -> float4 0/1

    const int tid  = threadIdx.x;
    const int lane = tid & 31;
    const int w    = tid >> 5;
    const int b    = blockIdx.y;
    const int tblk = blockIdx.x * (8 * LB_);

    for (int i = tid; i < NH * 32; i += 256) {
        int c = i >> 5, l = i & 31, e0 = l * 2;
        ws4[i] = make_float4(w2[(e0 * NH + c) * 3 + 0], w2[((e0 + 1) * NH + c) * 3 + 0],
                             w2[(e0 * NH + c) * 3 + 1], w2[((e0 + 1) * NH + c) * 3 + 1]);
        ws2[i] = make_float2(w2[(e0 * NH + c) * 3 + 2], w2[((e0 + 1) * NH + c) * 3 + 2]);
    }
    for (int j = tid; j < MSZ; j += 256) {
        int t = tblk + j - 35;                     // ms[j] <-> mask word at time t
        ms[j] = ((unsigned)t < (unsigned)T_) ? g_mask[(size_t)b * T_ + t] : 0u;
    }
    if (tid < 16)
        lut16[tid] = make_float4((float)(tid & 1), (float)((tid >> 1) & 1),
                                 (float)((tid >> 2) & 1), (float)((tid >> 3) & 1));
    __syncthreads();

    const int segg = blockIdx.x * 8 + w;     // global 256-step segment id
    const int t0   = tblk + w * LB_;
    const unsigned* msw = ms + w * LB_;      // msw[j] <-> time t0 + j - 35
    const int e0   = lane * 2;

    const float sc0 = __fmul_rn(g2[e0],     __frsqrt_rn(__fadd_rn(v2[e0],     1e-5f)));
    const float sh0 = __fsub_rn(be2[e0],     __fmul_rn(m2[e0],     sc0));
    const float sc1 = __fmul_rn(g2[e0 + 1], __frsqrt_rn(__fadd_rn(v2[e0 + 1], 1e-5f)));
    const float sh1 = __fsub_rn(be2[e0 + 1], __fmul_rn(m2[e0 + 1], sc1));
    const u64 sc2 = pk2(sc0, sc1);
    const u64 sh2 = pk2(__fmaf_rn(b2[e0], sc0, sh0), __fmaf_rn(b2[e0 + 1], sc1, sh1));

    u64 aA = 0ull, aB = 0ull, aC = 0ull, aD = 0ull;   // packed (e0,e1) accumulators
    float vr0 = 0.f, vr1 = 0.f;                        // post-reset membranes
    unsigned me = 0, mo = 0;

    // Prime: word m[ts-1] -> tap0 to first emit acc; word m[ts] -> tap1 + tap0.
    const int pj = (segg == 0) ? 34 : 2;     // seg0: words t0-1,t0 ; else t0-33,t0-32
    { unsigned r = msw[pj];
      while (r) { int c = __ffs(r) - 1; r &= r - 1;
          ulonglong2 q = *(const ulonglong2*)&ws4[(c << 5) + lane];
          aA = add2_(aA, q.x); } }
    { unsigned r = msw[pj + 1];
      while (r) { int c = __ffs(r) - 1; r &= r - 1;
          ulonglong2 q = *(const ulonglong2*)&ws4[(c << 5) + lane];
          aA = add2_(aA, q.y);
          aB = add2_(aB, q.x); } }

#define KB_BIT(P_,Q_,R_) { \
    int c = __ffs(r) - 1; r &= r - 1; \
    ulonglong2 q = *(const ulonglong2*)&ws4[(c << 5) + lane]; \
    u64 p = *(const u64*)&ws2[(c << 5) + lane]; \
    P_ = add2_(P_, p); \
    Q_ = add2_(Q_, q.y); \
    R_ = add2_(R_, q.x); }

    // One LIF step: P = finished acc (gets tap2), Q gets tap1, R fresh (tap0).
#define KB_ST(P_,Q_,R_, RM, DOEMIT, SI) { \
    R_ = 0ull; \
    unsigned r = (RM); \
    while (r) { \
        KB_BIT(P_,Q_,R_) \
        if (r) { KB_BIT(P_,Q_,R_) } \
    } \
    u64 u2 = fma2_(P_, sc2, sh2); \
    float u0, u1; upk2(u2, u0, u1); \
    float vp0 = __fmaf_rn(__fsub_rn(u0, vr0), 0.5f, vr0); \
    bool  s0_ = (vp0 >= 1.0f);  vr0 = s0_ ? 0.0f : vp0; \
    float vp1 = __fmaf_rn(__fsub_rn(u1, vr1), 0.5f, vr1); \
    bool  s1_ = (vp1 >= 1.0f);  vr1 = s1_ ? 0.0f : vp1; \
    if (DOEMIT) { if (s0_) me |= (1u << (SI)); \
                  if (s1_) mo |= (1u << (SI)); } }

#define KB_QUAD(JQ, DOEMIT, SB) { \
    uint4 m4 = *(const uint4*)&msw[JQ]; \
    KB_ST(aA, aB, aC, m4.x, DOEMIT, (SB) + 0) \
    KB_ST(aB, aC, aD, m4.y, DOEMIT, (SB) + 1) \
    KB_ST(aC, aD, aA, m4.z, DOEMIT, (SB) + 2) \
    KB_ST(aD, aA, aB, m4.w, DOEMIT, (SB) + 3) }

    if (segg != 0) {
#pragma unroll 1
        for (int q = 0; q < 8; q++) KB_QUAD(4 + q * 4, 0, 0)      // 32 warm steps
    }

    float* ob = out + (size_t)b * NE * T_ + t0;
#pragma unroll 1
    for (int g = 0; g < 8; g++) {
        const int jb = 36 + g * 32;
#pragma unroll 1
        for (int q = 0; q < 8; q++) KB_QUAD(jb + q * 4, 1, q * 4)  // 32 emit steps

        *(uint2*)&es[w][e0] = make_uint2(me, mo);
        __syncwarp();
#pragma unroll
        for (int i = 0; i < 16; i++) {
            int idx = i * 32 + lane;          // 0..511
            int e   = idx >> 3;               // 0..63
            int q4  = (idx & 7) * 4;          // 0,4,..,28
            float4 v = lut16[(es[w][e] >> q4) & 0xF];
            *(float4*)&ob[(size_t)e * T_ + g * 32 + q4] = v;
        }
        __syncwarp();
        me = 0; mo = 0;
    }
#undef KB_QUAD
#undef KB_ST
#undef KB_BIT
}

// ---------------------------------------------------------------------------
extern "C" void kernel_launch(void* const* d_in, const int* in_sizes, int n_in,
                              void* d_out, int out_size)
{
    const float* x   = (const float*)d_in[0];
    const float* w1  = (const float*)d_in[1];
    const float* b1  = (const float*)d_in[2];
    const float* g1  = (const float*)d_in[3];
    const float* be1 = (const float*)d_in[4];
    const float* m1  = (const float*)d_in[5];
    const float* v1  = (const float*)d_in[6];
    const float* w2  = (const float*)d_in[7];
    const float* b2  = (const float*)d_in[8];
    const float* g2  = (const float*)d_in[9];
    const float* be2 = (const float*)d_in[10];
    const float* m2  = (const float*)d_in[11];
    const float* v2  = (const float*)d_in[12];
    float* out = (float*)d_out;

    // Max L1/smem carveout: kB needs 5 x 35KB = 175KB/SM for single-wave
    // residency.  Host-side attribute -> graph-capture-safe; idempotent.
    cudaFuncSetAttribute((const void*)kA,
                         cudaFuncAttributePreferredSharedMemoryCarveout,
                         cudaSharedmemCarveoutMaxShared);
    cudaFuncSetAttribute((const void*)kB,
                         cudaFuncAttributePreferredSharedMemoryCarveout,
                         cudaSharedmemCarveoutMaxShared);

    kA<<<dim3(64, 64), 32>>>(x, w1, b1, g1, be1, m1, v1);
    kB<<<dim3(8, 64), 256>>>(w2, b2, g2, be2, m2, v2, out);
}